// round 12
// baseline (speedup 1.0000x reference)
#include <cuda_runtime.h>
#include <cuda_fp16.h>
#include <math.h>
#include <stdint.h>

#define BATCH 2048
#define HDIM  1024
#define G3    3072
#define NMSG  4096

// ---------------- scratch (static device globals; no allocation) ----------------
__device__ float g_Hin[7LL * BATCH * HDIM];
__device__ float g_Hv[(long)BATCH * HDIM];
__device__ float g_gh[(long)BATCH * G3];
__device__ float g_giAll[13LL * BATCH * G3];
__device__ __align__(16) __half g_HinR[(long)BATCH * HDIM];   // fp16 A for GRU1
__device__ __align__(16) __half g_HvR[(long)BATCH * HDIM];    // fp16 A for GRU2/msg/out
__device__ __align__(16) __half g_Xpad[13LL * BATCH * 32];
__device__ __align__(16) __half g_Wx32[3LL * G3 * 32];
__device__ __align__(16) __half g_Whh3R[3LL * G3 * HDIM];     // [c|l|r]
__device__ __align__(16) __half g_WmsgQ[(long)NMSG * HDIM];   // quad-interleaved
__device__ __align__(16) __half g_WoutR[512L * HDIM];         // [Wmu;Wstd]
__device__ float g_bout[512];                                  // [bmu;bstd]

__device__ __forceinline__ float sigmoidf(float x) { return 1.f / (1.f + expf(-x)); }
__device__ __forceinline__ float softplusf(float x) {
    return (x > 20.f) ? x : log1pf(expf(x));
}

// ---------------- packing (emit fp16 operands) ----------------
__global__ void pack_xpad(const float* __restrict__ X, const int* __restrict__ adj,
                          __half* __restrict__ Xp) {
    int idx = blockIdx.x * blockDim.x + threadIdx.x;
    if (idx >= 13 * BATCH * 32) return;
    int slot = idx / (BATCH * 32);
    int rem  = idx - slot * (BATCH * 32);
    int b = rem >> 5, k = rem & 31;
    float v = 0.f;
    if (slot < 6) {
        int node = slot + 1;
        if (k < 27) v = X[(long)b * 189 + node * 27 + k];
    } else if (slot < 12) {
        int node = slot - 5;
        if (k < 27 && adj[(long)b * 49 + node * 8] > 0)
            v = X[(long)b * 189 + node * 27 + k];
    } else {
        if (k < 23) v = X[(long)b * 189 + k];
    }
    Xp[idx] = __float2half_rn(v);
}

__global__ void pack_wx32(const float* __restrict__ W, __half* __restrict__ P, int K) {
    int idx = blockIdx.x * blockDim.x + threadIdx.x;
    if (idx >= G3 * 32) return;
    int j = idx >> 5, k = idx & 31;
    P[idx] = __float2half_rn((k < K) ? W[j * K + k] : 0.f);
}

// quad-interleaved msg weights: row (4h+q), q = A:Wg1 B:Wg2 C:Wm1 D:Wm2
__global__ void pack_msgw_quad(const float* __restrict__ Wg, const float* __restrict__ Wm,
                               __half* __restrict__ P) {
    int idx = blockIdx.x * blockDim.x + threadIdx.x;   // 4096*1024
    int jn = idx >> 10, k = idx & 1023;
    int h = jn >> 2, q = jn & 3;
    float v;
    if (q == 0)      v = Wg[h * 2048 + k];
    else if (q == 1) v = Wg[h * 2048 + 1024 + k];
    else if (q == 2) v = Wm[h * 2048 + k];
    else             v = Wm[h * 2048 + 1024 + k];
    P[idx] = __float2half_rn(v);
}

__global__ void half_copy3(const float* __restrict__ a, const float* __restrict__ b,
                           const float* __restrict__ c, __half* __restrict__ out,
                           int n) {
    int idx = blockIdx.x * blockDim.x + threadIdx.x;
    if (idx >= 3 * n) return;
    int seg = idx / n, r = idx - seg * n;
    const float* src = (seg == 0) ? a : (seg == 1) ? b : c;
    out[idx] = __float2half_rn(src[r]);
}

__global__ void half_copy2(const float* __restrict__ a, const float* __restrict__ b,
                           __half* __restrict__ out, int n) {
    int idx = blockIdx.x * blockDim.x + threadIdx.x;
    if (idx >= 2 * n) return;
    out[idx] = __float2half_rn(idx < n ? a[idx] : b[idx - n]);
}

// ---------------- GRU elementwise combine (+ fp16 copy) ----------------
template<int WRITE_HO>
__global__ __launch_bounds__(256) void gru_combine_r(
    const float* __restrict__ gi, const float* __restrict__ gh,
    const float* __restrict__ hp, float* __restrict__ ho,
    __half* __restrict__ hoR)
{
    int idx = blockIdx.x * 256 + threadIdx.x;
    int b = idx >> 10, h = idx & 1023;
    long base = (long)b * G3 + h;
    float ir = gi[base], iz = gi[base + 1024], in_ = gi[base + 2048];
    float hr = gh[base], hz = gh[base + 1024], hn = gh[base + 2048];
    float r = sigmoidf(ir + hr);
    float z = sigmoidf(iz + hz);
    float n = tanhf(in_ + r * hn);
    float o = (1.f - z) * n + z * hp[idx];
    if (WRITE_HO) ho[idx] = o;
    hoR[idx] = __float2half_rn(o);
}

// v=6 GRU1: gh = bias (H_in = 0), hp = 0
__global__ __launch_bounds__(256) void gru_combine_bias(
    const float* __restrict__ gi, const float* __restrict__ bhh,
    float* __restrict__ ho, __half* __restrict__ hoR)
{
    int idx = blockIdx.x * 256 + threadIdx.x;
    int b = idx >> 10, h = idx & 1023;
    long base = (long)b * G3 + h;
    float ir = gi[base], iz = gi[base + 1024], in_ = gi[base + 2048];
    float hr = bhh[h], hz = bhh[1024 + h], hn = bhh[2048 + h];
    float r = sigmoidf(ir + hr);
    float z = sigmoidf(iz + hz);
    float n = tanhf(in_ + r * hn);
    float o = (1.f - z) * n;
    ho[idx]  = o;
    hoR[idx] = __float2half_rn(o);
}

// ---------------- fp16 mma.sync GEMM: C[M,N] = A[M,K] * B[N,K]^T ----------------
#define BM 128
#define BN 128
#define KS 20   // row stride in u32 (16 data + 4 pad)

__global__ __launch_bounds__(256, 2) void hgemm_nt(
    const __half* __restrict__ A, const __half* __restrict__ B,
    const float* __restrict__ bias, float* __restrict__ C,
    int N, int K, int act)
{
    __shared__ unsigned As[2][BM][KS];
    __shared__ unsigned Bs[2][BN][KS];

    const int tid  = threadIdx.x;
    const int lane = tid & 31;
    const int warp = tid >> 5;
    const int wm   = warp >> 1;
    const int wn   = warp & 1;
    const long bm  = (long)blockIdx.y * BM;
    const long bn  = (long)blockIdx.x * BN;

    const int lrow = tid >> 2;
    const int lcolh = (tid & 3) << 3;
    const int lcolu = (tid & 3) << 2;
    const __half* Aptr = A + (bm + lrow) * K + lcolh;
    const __half* Bptr = B + (bn + lrow) * K + lcolh;

    float acc[2][8][4];
#pragma unroll
    for (int i = 0; i < 2; i++)
#pragma unroll
        for (int j = 0; j < 8; j++)
#pragma unroll
            for (int q = 0; q < 4; q++) acc[i][j][q] = 0.f;

    {
#pragma unroll
        for (int r = 0; r < 2; r++) {
            *(uint4*)&As[0][lrow + r * 64][lcolu] =
                *(const uint4*)(Aptr + (long)(r * 64) * K);
            *(uint4*)&Bs[0][lrow + r * 64][lcolu] =
                *(const uint4*)(Bptr + (long)(r * 64) * K);
        }
    }
    __syncthreads();

    const int nt = K / 32;
    const int gr = lane >> 2;
    const int gk = lane & 3;
    uint4 pa[2], pb[2];

    for (int t = 0; t < nt; t++) {
        const int cur = t & 1, nxt = cur ^ 1;
        const bool more = (t + 1 < nt);
        if (more) {
            int koff = (t + 1) * 32;
#pragma unroll
            for (int r = 0; r < 2; r++) {
                pa[r] = *(const uint4*)(Aptr + (long)(r * 64) * K + koff);
                pb[r] = *(const uint4*)(Bptr + (long)(r * 64) * K + koff);
            }
        }
#pragma unroll
        for (int k16 = 0; k16 < 2; k16++) {
            const int kb = k16 * 8;
            unsigned a[2][4], b[8][2];
#pragma unroll
            for (int mt = 0; mt < 2; mt++) {
                int m = wm * 32 + mt * 16 + gr;
                a[mt][0] = As[cur][m][kb + gk];
                a[mt][1] = As[cur][m + 8][kb + gk];
                a[mt][2] = As[cur][m][kb + gk + 4];
                a[mt][3] = As[cur][m + 8][kb + gk + 4];
            }
#pragma unroll
            for (int ntile = 0; ntile < 8; ntile++) {
                int n = wn * 64 + ntile * 8 + gr;
                b[ntile][0] = Bs[cur][n][kb + gk];
                b[ntile][1] = Bs[cur][n][kb + gk + 4];
            }
#pragma unroll
            for (int mt = 0; mt < 2; mt++)
#pragma unroll
                for (int ntile = 0; ntile < 8; ntile++) {
                    asm volatile(
                        "mma.sync.aligned.m16n8k16.row.col.f32.f16.f16.f32 "
                        "{%0,%1,%2,%3}, {%4,%5,%6,%7}, {%8,%9}, {%0,%1,%2,%3};\n"
                        : "+f"(acc[mt][ntile][0]), "+f"(acc[mt][ntile][1]),
                          "+f"(acc[mt][ntile][2]), "+f"(acc[mt][ntile][3])
                        : "r"(a[mt][0]), "r"(a[mt][1]), "r"(a[mt][2]), "r"(a[mt][3]),
                          "r"(b[ntile][0]), "r"(b[ntile][1]));
                }
        }
        if (more) {
#pragma unroll
            for (int r = 0; r < 2; r++) {
                *(uint4*)&As[nxt][lrow + r * 64][lcolu] = pa[r];
                *(uint4*)&Bs[nxt][lrow + r * 64][lcolu] = pb[r];
            }
        }
        __syncthreads();
    }

    const int gc2 = (lane & 3) * 2;
#pragma unroll
    for (int mt = 0; mt < 2; mt++) {
        long row0 = bm + wm * 32 + mt * 16 + gr;
#pragma unroll
        for (int ntile = 0; ntile < 8; ntile++) {
            int col = bn + wn * 64 + ntile * 8 + gc2;
            float b0 = bias ? bias[col] : 0.f;
            float b1 = bias ? bias[col + 1] : 0.f;
            float2 v0, v1;
            v0.x = acc[mt][ntile][0] + b0; v0.y = acc[mt][ntile][1] + b1;
            v1.x = acc[mt][ntile][2] + b0; v1.y = acc[mt][ntile][3] + b1;
            if (act == 2) {
                float* dst;
                if (col < 256) {
                    dst = C + row0 * 256 + col;
                } else {
                    dst = C + 2048L * 256 + row0 * 256 + (col - 256);
                    v0.x = softplusf(v0.x); v0.y = softplusf(v0.y);
                    v1.x = softplusf(v1.x); v1.y = softplusf(v1.y);
                }
                *(float2*)dst             = v0;
                *(float2*)(dst + 8 * 256) = v1;
            } else {
                *(float2*)(C + row0 * N + col)       = v0;
                *(float2*)(C + (row0 + 8) * N + col) = v1;
            }
        }
    }
}

// ======== fused msg GEMM + scatter: quad-interleaved weights, smem-staged ========
// A = HvR [2048,1024] fp16; B = WmsgQ [4096,1024] fp16 (row 4h+q).
// CTA tile: 128 batch rows x 128 cols (= 32 h-quadruples). After GEMM, stage the
// f32 tile in smem, then scatter g*m contributions into Hin[u] for u < S, and
// write HinR fp16 for u = S-1 (the next node's GEMM operand).
#define STG_STRIDE 132
#define MSG_SMEM (2*BM*KS*4 + 2*BN*KS*4 + BM*STG_STRIDE*4)   // 40960 + 67584

__global__ __launch_bounds__(256, 2) void msg_gemm_scatter(
    const __half* __restrict__ A, const __half* __restrict__ B,
    const float* __restrict__ bg, const int* __restrict__ adj,
    float* __restrict__ Hin, __half* __restrict__ HinR, int S)
{
    extern __shared__ char dsm[];
    unsigned (*As)[BM][KS] = (unsigned (*)[BM][KS])dsm;
    unsigned (*Bs)[BN][KS] = (unsigned (*)[BN][KS])(dsm + 2 * BM * KS * 4);
    float* stg = (float*)(dsm + 2 * BM * KS * 4 + 2 * BN * KS * 4);

    const int tid  = threadIdx.x;
    const int lane = tid & 31;
    const int warp = tid >> 5;
    const int wm   = warp >> 1;
    const int wn   = warp & 1;
    const long bm  = (long)blockIdx.y * BM;
    const long bn  = (long)blockIdx.x * BN;
    const int K    = 1024;

    const int lrow = tid >> 2;
    const int lcolh = (tid & 3) << 3;
    const int lcolu = (tid & 3) << 2;
    const __half* Aptr = A + (bm + lrow) * K + lcolh;
    const __half* Bptr = B + (bn + lrow) * K + lcolh;

    float acc[2][8][4];
#pragma unroll
    for (int i = 0; i < 2; i++)
#pragma unroll
        for (int j = 0; j < 8; j++)
#pragma unroll
            for (int q = 0; q < 4; q++) acc[i][j][q] = 0.f;

    {
#pragma unroll
        for (int r = 0; r < 2; r++) {
            *(uint4*)&As[0][lrow + r * 64][lcolu] =
                *(const uint4*)(Aptr + (long)(r * 64) * K);
            *(uint4*)&Bs[0][lrow + r * 64][lcolu] =
                *(const uint4*)(Bptr + (long)(r * 64) * K);
        }
    }
    __syncthreads();

    const int gr = lane >> 2;
    const int gk = lane & 3;
    uint4 pa[2], pb[2];

    for (int t = 0; t < 32; t++) {
        const int cur = t & 1, nxt = cur ^ 1;
        const bool more = (t + 1 < 32);
        if (more) {
            int koff = (t + 1) * 32;
#pragma unroll
            for (int r = 0; r < 2; r++) {
                pa[r] = *(const uint4*)(Aptr + (long)(r * 64) * K + koff);
                pb[r] = *(const uint4*)(Bptr + (long)(r * 64) * K + koff);
            }
        }
#pragma unroll
        for (int k16 = 0; k16 < 2; k16++) {
            const int kb = k16 * 8;
            unsigned a[2][4], b[8][2];
#pragma unroll
            for (int mt = 0; mt < 2; mt++) {
                int m = wm * 32 + mt * 16 + gr;
                a[mt][0] = As[cur][m][kb + gk];
                a[mt][1] = As[cur][m + 8][kb + gk];
                a[mt][2] = As[cur][m][kb + gk + 4];
                a[mt][3] = As[cur][m + 8][kb + gk + 4];
            }
#pragma unroll
            for (int ntile = 0; ntile < 8; ntile++) {
                int n = wn * 64 + ntile * 8 + gr;
                b[ntile][0] = Bs[cur][n][kb + gk];
                b[ntile][1] = Bs[cur][n][kb + gk + 4];
            }
#pragma unroll
            for (int mt = 0; mt < 2; mt++)
#pragma unroll
                for (int ntile = 0; ntile < 8; ntile++) {
                    asm volatile(
                        "mma.sync.aligned.m16n8k16.row.col.f32.f16.f16.f32 "
                        "{%0,%1,%2,%3}, {%4,%5,%6,%7}, {%8,%9}, {%0,%1,%2,%3};\n"
                        : "+f"(acc[mt][ntile][0]), "+f"(acc[mt][ntile][1]),
                          "+f"(acc[mt][ntile][2]), "+f"(acc[mt][ntile][3])
                        : "r"(a[mt][0]), "r"(a[mt][1]), "r"(a[mt][2]), "r"(a[mt][3]),
                          "r"(b[ntile][0]), "r"(b[ntile][1]));
                }
        }
        if (more) {
#pragma unroll
            for (int r = 0; r < 2; r++) {
                *(uint4*)&As[nxt][lrow + r * 64][lcolu] = pa[r];
                *(uint4*)&Bs[nxt][lrow + r * 64][lcolu] = pb[r];
            }
        }
        __syncthreads();
    }

    // stage the f32 tile
    const int gc2 = (lane & 3) * 2;
#pragma unroll
    for (int mt = 0; mt < 2; mt++) {
        int rl = wm * 32 + mt * 16 + gr;
#pragma unroll
        for (int ntile = 0; ntile < 8; ntile++) {
            int col = wn * 64 + ntile * 8 + gc2;
            *(float2*)&stg[rl * STG_STRIDE + col] =
                make_float2(acc[mt][ntile][0], acc[mt][ntile][1]);
            *(float2*)&stg[(rl + 8) * STG_STRIDE + col] =
                make_float2(acc[mt][ntile][2], acc[mt][ntile][3]);
        }
    }
    __syncthreads();

    // scatter: warp handles one row, lanes cover the 32 h's of this CTA
    const int hg = blockIdx.x * 32 + lane;
    const float bgh = bg[hg];
    for (int it = 0; it < 16; it++) {
        int row = warp + it * 8;                 // 0..127
        long b  = bm + row;
        float4 q = *(float4*)&stg[row * STG_STRIDE + lane * 4];  // A,B,C,D
        float c10 = sigmoidf(q.x + bgh) * q.z;
        float c01 = sigmoidf(q.y + bgh) * q.w;
        float c11 = sigmoidf(q.x + q.y + bgh) * (q.z + q.w);
        const int* arow = adj + b * 49;
        for (int u = 0; u < S; u++) {
            bool fp = arow[S * 7 + u] > 0;
            bool fs = arow[u * 7 + S] > 0;
            float add = fp ? (fs ? c11 : c10) : (fs ? c01 : 0.f);
            long o = (long)u * BATCH * HDIM + b * HDIM + hg;
            float val = Hin[o] + add;
            Hin[o] = val;
            if (u == S - 1) HinR[b * HDIM + hg] = __float2half_rn(val);
        }
    }
}

// ---------------- orchestration ----------------
extern "C" void kernel_launch(void* const* d_in, const int* in_sizes, int n_in,
                              void* d_out, int out_size)
{
    const float* X      = (const float*)d_in[0];
    const int*   adj    = (const int*)  d_in[1];
    const float* W_ih_c = (const float*)d_in[2];
    const float* W_hh_c = (const float*)d_in[3];
    const float* b_ih_c = (const float*)d_in[4];
    const float* b_hh_c = (const float*)d_in[5];
    const float* W_ih_l = (const float*)d_in[6];
    const float* W_hh_l = (const float*)d_in[7];
    const float* b_ih_l = (const float*)d_in[8];
    const float* b_hh_l = (const float*)d_in[9];
    const float* W_ih_r = (const float*)d_in[10];
    const float* W_hh_r = (const float*)d_in[11];
    const float* b_ih_r = (const float*)d_in[12];
    const float* b_hh_r = (const float*)d_in[13];
    const float* Wg     = (const float*)d_in[14];
    const float* bg     = (const float*)d_in[15];
    const float* Wm     = (const float*)d_in[16];
    const float* Wmu    = (const float*)d_in[17];
    const float* bmu    = (const float*)d_in[18];
    const float* Wstd   = (const float*)d_in[19];
    const float* bstd   = (const float*)d_in[20];

    float *Hin, *Hv, *gh, *giAll, *bout;
    __half *HinR, *HvR, *Xpad, *Wx32, *Whh3R, *WmsgQ, *WoutR;
    cudaGetSymbolAddress((void**)&Hin,   g_Hin);
    cudaGetSymbolAddress((void**)&Hv,    g_Hv);
    cudaGetSymbolAddress((void**)&gh,    g_gh);
    cudaGetSymbolAddress((void**)&giAll, g_giAll);
    cudaGetSymbolAddress((void**)&bout,  g_bout);
    cudaGetSymbolAddress((void**)&HinR,  g_HinR);
    cudaGetSymbolAddress((void**)&HvR,   g_HvR);
    cudaGetSymbolAddress((void**)&Xpad,  g_Xpad);
    cudaGetSymbolAddress((void**)&Wx32,  g_Wx32);
    cudaGetSymbolAddress((void**)&Whh3R, g_Whh3R);
    cudaGetSymbolAddress((void**)&WmsgQ, g_WmsgQ);
    cudaGetSymbolAddress((void**)&WoutR, g_WoutR);

    __half* WhhcR = Whh3R;
    __half* WhhlR = Whh3R + (long)G3 * HDIM;
    __half* WhhrR = Whh3R + 2L * G3 * HDIM;

    cudaFuncSetAttribute(msg_gemm_scatter,
                         cudaFuncAttributeMaxDynamicSharedMemorySize, MSG_SMEM);

    cudaMemsetAsync(Hin, 0, sizeof(float) * 7LL * BATCH * HDIM, 0);

    pack_xpad<<<(13 * BATCH * 32) / 256, 256>>>(X, adj, Xpad);
    pack_wx32<<<(G3 * 32) / 256, 256>>>(W_ih_c, Wx32,               27);
    pack_wx32<<<(G3 * 32) / 256, 256>>>(W_ih_l, Wx32 + (long)G3*32, 27);
    pack_wx32<<<(G3 * 32) / 256, 256>>>(W_ih_r, Wx32 + 2L*G3*32,    23);
    pack_msgw_quad<<<(NMSG * HDIM) / 256, 256>>>(Wg, Wm, WmsgQ);

    half_copy3<<<(3 * G3 * HDIM) / 256, 256>>>(W_hh_c, W_hh_l, W_hh_r,
                                               Whh3R, G3 * HDIM);
    half_copy2<<<(2 * 256 * HDIM) / 256, 256>>>(Wmu, Wstd, WoutR, 256 * HDIM);
    cudaMemcpyAsync(bout,       bmu,  256 * sizeof(float), cudaMemcpyDeviceToDevice, 0);
    cudaMemcpyAsync(bout + 256, bstd, 256 * sizeof(float), cudaMemcpyDeviceToDevice, 0);

    // gi projections (K=32 halves -> single K-tile)
    const long SEG = 6LL * BATCH;
    dim3 gGI6(G3 / BN, (6 * BATCH) / BM);
    dim3 gGI1(G3 / BN, BATCH / BM);
    hgemm_nt<<<gGI6, 256>>>(Xpad,                Wx32,               b_ih_c,
                            giAll,               G3, 32, 0);
    hgemm_nt<<<gGI6, 256>>>(Xpad + SEG * 32,     Wx32 + (long)G3*32, b_ih_l,
                            giAll + SEG * G3,    G3, 32, 0);
    hgemm_nt<<<gGI1, 256>>>(Xpad + 2 * SEG * 32, Wx32 + 2L*G3*32,    b_ih_r,
                            giAll + 2 * SEG * G3, G3, 32, 0);

    dim3 gGH(G3 / BN, BATCH / BM);             // (24, 16)
    dim3 gMS(NMSG / BN, BATCH / BM);           // (32, 16)
    dim3 gOUT(512 / BN, BATCH / BM);           // (4, 16)
    const int EW = (BATCH * HDIM) / 256;       // 8192

    for (int v = 6; v >= 0; v--) {
        const __half* WhhR = (v == 0) ? WhhrR : WhhcR;
        const float* bhh   = (v == 0) ? b_hh_r : b_hh_c;
        const float* gi1   = (v == 0) ? (giAll + 2 * SEG * G3)
                                      : (giAll + (long)(v - 1) * BATCH * G3);

        // GRU 1
        if (v == 6) {
            gru_combine_bias<<<EW, 256>>>(gi1, bhh, Hv, HvR);
        } else {
            float* Hin_v = Hin + (long)v * BATCH * HDIM;
            hgemm_nt<<<gGH, 256>>>(HinR, WhhR, bhh, gh, G3, HDIM, 0);
            if (v == 0) {
                gru_combine_r<0><<<EW, 256>>>(gi1, gh, Hin_v, Hv, HvR);
            } else {
                gru_combine_r<1><<<EW, 256>>>(gi1, gh, Hin_v, Hv, HvR);
            }
        }

        if (v > 0) {
            // GRU 2 (self-loop)
            const float* gi2 = giAll + (SEG + (long)(v - 1) * BATCH) * G3;
            hgemm_nt<<<gGH, 256>>>(HvR, WhhlR, b_hh_l, gh, G3, HDIM, 0);
            gru_combine_r<0><<<EW, 256>>>(gi2, gh, Hv, Hv, HvR);

            // fused sender projections + scatter (+ fp16 HinR for u=v-1)
            msg_gemm_scatter<<<gMS, 256, MSG_SMEM>>>(HvR, WmsgQ, bg, adj,
                                                     Hin, HinR, v);
        }
    }

    // fused mu/std output GEMM (act=2 split epilogue)
    hgemm_nt<<<gOUT, 256>>>(HvR, WoutR, bout, (float*)d_out, 512, HDIM, 2);
}

// round 13
// speedup vs baseline: 1.1577x; 1.1577x over previous
#include <cuda_runtime.h>
#include <cuda_fp16.h>
#include <math.h>
#include <stdint.h>

#define BATCH 2048
#define HDIM  1024
#define G3    3072
#define NMSG  4096

// ---------------- scratch (static device globals; no allocation) ----------------
__device__ float g_Hin[7LL * BATCH * HDIM];
__device__ float g_Hv[(long)BATCH * HDIM];
__device__ float g_gh[(long)BATCH * G3];
__device__ __align__(16) __half g_msg[(long)BATCH * NMSG];    // fp16 staging
__device__ __align__(16) __half g_giAll[13LL * BATCH * G3];   // fp16 staging
__device__ __align__(16) __half g_HinR[(long)BATCH * HDIM];   // fp16 A for GRU1
__device__ __align__(16) __half g_HvR[(long)BATCH * HDIM];    // fp16 A for GRU2/msg/out
__device__ __align__(16) __half g_Xpad[13LL * BATCH * 32];
__device__ __align__(16) __half g_Wx32[3LL * G3 * 32];
__device__ __align__(16) __half g_Whh3R[3LL * G3 * HDIM];     // [c|l|r]
__device__ __align__(16) __half g_WmsgR[(long)NMSG * HDIM];
__device__ __align__(16) __half g_WoutR[512L * HDIM];         // [Wmu;Wstd]
__device__ float g_bout[512];                                  // [bmu;bstd]

__device__ __forceinline__ float sigmoidf(float x) { return 1.f / (1.f + expf(-x)); }
__device__ __forceinline__ float softplusf(float x) {
    return (x > 20.f) ? x : log1pf(expf(x));
}

// ---------------- packing (emit fp16 operands) ----------------
__global__ void pack_xpad(const float* __restrict__ X, const int* __restrict__ adj,
                          __half* __restrict__ Xp) {
    int idx = blockIdx.x * blockDim.x + threadIdx.x;
    if (idx >= 13 * BATCH * 32) return;
    int slot = idx / (BATCH * 32);
    int rem  = idx - slot * (BATCH * 32);
    int b = rem >> 5, k = rem & 31;
    float v = 0.f;
    if (slot < 6) {
        int node = slot + 1;
        if (k < 27) v = X[(long)b * 189 + node * 27 + k];
    } else if (slot < 12) {
        int node = slot - 5;
        if (k < 27 && adj[(long)b * 49 + node * 8] > 0)
            v = X[(long)b * 189 + node * 27 + k];
    } else {
        if (k < 23) v = X[(long)b * 189 + k];
    }
    Xp[idx] = __float2half_rn(v);
}

__global__ void pack_wx32(const float* __restrict__ W, __half* __restrict__ P, int K) {
    int idx = blockIdx.x * blockDim.x + threadIdx.x;
    if (idx >= G3 * 32) return;
    int j = idx >> 5, k = idx & 31;
    P[idx] = __float2half_rn((k < K) ? W[j * K + k] : 0.f);
}

__global__ void pack_msgw(const float* __restrict__ Wg, const float* __restrict__ Wm,
                          __half* __restrict__ P) {
    int idx = blockIdx.x * blockDim.x + threadIdx.x;
    int j = idx >> 10, k = idx & 1023;
    float v;
    if (j < 1024)       v = Wg[j * 2048 + k];
    else if (j < 2048)  v = Wg[(j - 1024) * 2048 + 1024 + k];
    else if (j < 3072)  v = Wm[(j - 2048) * 2048 + k];
    else                v = Wm[(j - 3072) * 2048 + 1024 + k];
    P[idx] = __float2half_rn(v);
}

__global__ void half_copy3(const float* __restrict__ a, const float* __restrict__ b,
                           const float* __restrict__ c, __half* __restrict__ out,
                           int n) {
    int idx = blockIdx.x * blockDim.x + threadIdx.x;
    if (idx >= 3 * n) return;
    int seg = idx / n, r = idx - seg * n;
    const float* src = (seg == 0) ? a : (seg == 1) ? b : c;
    out[idx] = __float2half_rn(src[r]);
}

__global__ void half_copy2(const float* __restrict__ a, const float* __restrict__ b,
                           __half* __restrict__ out, int n) {
    int idx = blockIdx.x * blockDim.x + threadIdx.x;
    if (idx >= 2 * n) return;
    out[idx] = __float2half_rn(idx < n ? a[idx] : b[idx - n]);
}

// ---------------- GRU elementwise combine (+ fp16 copy); gi is fp16 ----------------
template<int WRITE_HO>
__global__ __launch_bounds__(256) void gru_combine_r(
    const __half* __restrict__ gi, const float* __restrict__ gh,
    const float* __restrict__ hp, float* __restrict__ ho,
    __half* __restrict__ hoR)
{
    int idx = blockIdx.x * 256 + threadIdx.x;
    int b = idx >> 10, h = idx & 1023;
    long base = (long)b * G3 + h;
    float ir = __half2float(gi[base]);
    float iz = __half2float(gi[base + 1024]);
    float in_ = __half2float(gi[base + 2048]);
    float hr = gh[base], hz = gh[base + 1024], hn = gh[base + 2048];
    float r = sigmoidf(ir + hr);
    float z = sigmoidf(iz + hz);
    float n = tanhf(in_ + r * hn);
    float o = (1.f - z) * n + z * hp[idx];
    if (WRITE_HO) ho[idx] = o;
    hoR[idx] = __float2half_rn(o);
}

// v=6 GRU1: gh = bias (H_in = 0), hp = 0
__global__ __launch_bounds__(256) void gru_combine_bias(
    const __half* __restrict__ gi, const float* __restrict__ bhh,
    float* __restrict__ ho, __half* __restrict__ hoR)
{
    int idx = blockIdx.x * 256 + threadIdx.x;
    int b = idx >> 10, h = idx & 1023;
    long base = (long)b * G3 + h;
    float ir = __half2float(gi[base]);
    float iz = __half2float(gi[base + 1024]);
    float in_ = __half2float(gi[base + 2048]);
    float hr = bhh[h], hz = bhh[1024 + h], hn = bhh[2048 + h];
    float r = sigmoidf(ir + hr);
    float z = sigmoidf(iz + hz);
    float n = tanhf(in_ + r * hn);
    float o = (1.f - z) * n;
    ho[idx]  = o;
    hoR[idx] = __float2half_rn(o);
}

// ---------------- message push: 3 combos precomputed; Mg is fp16 ----------
__global__ __launch_bounds__(256) void msg_scatter_all(
    const __half* __restrict__ Mg, const int* __restrict__ adj,
    const float* __restrict__ bg, float* __restrict__ HinBase,
    __half* __restrict__ HinR, int S)
{
    int idx = blockIdx.x * 256 + threadIdx.x;
    int b = idx >> 10, h = idx & 1023;
    const __half* M = Mg + (long)b * NMSG;
    float Av = __half2float(M[h]);
    float Bv = __half2float(M[1024 + h]);
    float Cv = __half2float(M[2048 + h]);
    float Dv = __half2float(M[3072 + h]);
    float bgh = bg[h];
    float c10 = sigmoidf(Av + bgh) * Cv;
    float c01 = sigmoidf(Bv + bgh) * Dv;
    float c11 = sigmoidf(Av + Bv + bgh) * (Cv + Dv);
    const int* arow = adj + (long)b * 49;
    for (int u = 0; u < S; u++) {
        bool fp = arow[S * 7 + u] > 0;
        bool fs = arow[u * 7 + S] > 0;
        float add = fp ? (fs ? c11 : c10) : (fs ? c01 : 0.f);
        long o = (long)u * BATCH * HDIM + idx;
        float val = HinBase[o] + add;
        HinBase[o] = val;
        if (u == S - 1) HinR[idx] = __float2half_rn(val);
    }
}

// ---------------- fp16 mma.sync GEMM: C[M,N] = A[M,K] * B[N,K]^T ----------------
// act: 0 = f32 out, 2 = split mu/std epilogue (f32), 3 = fp16 out.
#define BM 128
#define BN 128
#define KS 20   // row stride in u32 (16 data + 4 pad)

__global__ __launch_bounds__(256, 2) void hgemm_nt(
    const __half* __restrict__ A, const __half* __restrict__ B,
    const float* __restrict__ bias, float* __restrict__ C,
    int N, int K, int act)
{
    __shared__ unsigned As[2][BM][KS];
    __shared__ unsigned Bs[2][BN][KS];

    const int tid  = threadIdx.x;
    const int lane = tid & 31;
    const int warp = tid >> 5;
    const int wm   = warp >> 1;
    const int wn   = warp & 1;
    const long bm  = (long)blockIdx.y * BM;
    const long bn  = (long)blockIdx.x * BN;

    const int lrow = tid >> 2;
    const int lcolh = (tid & 3) << 3;
    const int lcolu = (tid & 3) << 2;
    const __half* Aptr = A + (bm + lrow) * K + lcolh;
    const __half* Bptr = B + (bn + lrow) * K + lcolh;

    float acc[2][8][4];
#pragma unroll
    for (int i = 0; i < 2; i++)
#pragma unroll
        for (int j = 0; j < 8; j++)
#pragma unroll
            for (int q = 0; q < 4; q++) acc[i][j][q] = 0.f;

    {
#pragma unroll
        for (int r = 0; r < 2; r++) {
            *(uint4*)&As[0][lrow + r * 64][lcolu] =
                *(const uint4*)(Aptr + (long)(r * 64) * K);
            *(uint4*)&Bs[0][lrow + r * 64][lcolu] =
                *(const uint4*)(Bptr + (long)(r * 64) * K);
        }
    }
    __syncthreads();

    const int nt = K / 32;
    const int gr = lane >> 2;
    const int gk = lane & 3;
    uint4 pa[2], pb[2];

    for (int t = 0; t < nt; t++) {
        const int cur = t & 1, nxt = cur ^ 1;
        const bool more = (t + 1 < nt);
        if (more) {
            int koff = (t + 1) * 32;
#pragma unroll
            for (int r = 0; r < 2; r++) {
                pa[r] = *(const uint4*)(Aptr + (long)(r * 64) * K + koff);
                pb[r] = *(const uint4*)(Bptr + (long)(r * 64) * K + koff);
            }
        }
#pragma unroll
        for (int k16 = 0; k16 < 2; k16++) {
            const int kb = k16 * 8;
            unsigned a[2][4], b[8][2];
#pragma unroll
            for (int mt = 0; mt < 2; mt++) {
                int m = wm * 32 + mt * 16 + gr;
                a[mt][0] = As[cur][m][kb + gk];
                a[mt][1] = As[cur][m + 8][kb + gk];
                a[mt][2] = As[cur][m][kb + gk + 4];
                a[mt][3] = As[cur][m + 8][kb + gk + 4];
            }
#pragma unroll
            for (int ntile = 0; ntile < 8; ntile++) {
                int n = wn * 64 + ntile * 8 + gr;
                b[ntile][0] = Bs[cur][n][kb + gk];
                b[ntile][1] = Bs[cur][n][kb + gk + 4];
            }
#pragma unroll
            for (int mt = 0; mt < 2; mt++)
#pragma unroll
                for (int ntile = 0; ntile < 8; ntile++) {
                    asm volatile(
                        "mma.sync.aligned.m16n8k16.row.col.f32.f16.f16.f32 "
                        "{%0,%1,%2,%3}, {%4,%5,%6,%7}, {%8,%9}, {%0,%1,%2,%3};\n"
                        : "+f"(acc[mt][ntile][0]), "+f"(acc[mt][ntile][1]),
                          "+f"(acc[mt][ntile][2]), "+f"(acc[mt][ntile][3])
                        : "r"(a[mt][0]), "r"(a[mt][1]), "r"(a[mt][2]), "r"(a[mt][3]),
                          "r"(b[ntile][0]), "r"(b[ntile][1]));
                }
        }
        if (more) {
#pragma unroll
            for (int r = 0; r < 2; r++) {
                *(uint4*)&As[nxt][lrow + r * 64][lcolu] = pa[r];
                *(uint4*)&Bs[nxt][lrow + r * 64][lcolu] = pb[r];
            }
        }
        __syncthreads();
    }

    const int gc2 = (lane & 3) * 2;
#pragma unroll
    for (int mt = 0; mt < 2; mt++) {
        long row0 = bm + wm * 32 + mt * 16 + gr;
#pragma unroll
        for (int ntile = 0; ntile < 8; ntile++) {
            int col = bn + wn * 64 + ntile * 8 + gc2;
            float b0 = bias ? bias[col] : 0.f;
            float b1 = bias ? bias[col + 1] : 0.f;
            float2 v0, v1;
            v0.x = acc[mt][ntile][0] + b0; v0.y = acc[mt][ntile][1] + b1;
            v1.x = acc[mt][ntile][2] + b0; v1.y = acc[mt][ntile][3] + b1;
            if (act == 3) {
                __half* Ch = (__half*)C;
                __half2 h0 = __floats2half2_rn(v0.x, v0.y);
                __half2 h1 = __floats2half2_rn(v1.x, v1.y);
                *(__half2*)(Ch + row0 * N + col)       = h0;
                *(__half2*)(Ch + (row0 + 8) * N + col) = h1;
            } else if (act == 2) {
                float* dst;
                if (col < 256) {
                    dst = C + row0 * 256 + col;
                } else {
                    dst = C + 2048L * 256 + row0 * 256 + (col - 256);
                    v0.x = softplusf(v0.x); v0.y = softplusf(v0.y);
                    v1.x = softplusf(v1.x); v1.y = softplusf(v1.y);
                }
                *(float2*)dst             = v0;
                *(float2*)(dst + 8 * 256) = v1;
            } else {
                *(float2*)(C + row0 * N + col)       = v0;
                *(float2*)(C + (row0 + 8) * N + col) = v1;
            }
        }
    }
}

// ---------------- orchestration ----------------
extern "C" void kernel_launch(void* const* d_in, const int* in_sizes, int n_in,
                              void* d_out, int out_size)
{
    const float* X      = (const float*)d_in[0];
    const int*   adj    = (const int*)  d_in[1];
    const float* W_ih_c = (const float*)d_in[2];
    const float* W_hh_c = (const float*)d_in[3];
    const float* b_ih_c = (const float*)d_in[4];
    const float* b_hh_c = (const float*)d_in[5];
    const float* W_ih_l = (const float*)d_in[6];
    const float* W_hh_l = (const float*)d_in[7];
    const float* b_ih_l = (const float*)d_in[8];
    const float* b_hh_l = (const float*)d_in[9];
    const float* W_ih_r = (const float*)d_in[10];
    const float* W_hh_r = (const float*)d_in[11];
    const float* b_ih_r = (const float*)d_in[12];
    const float* b_hh_r = (const float*)d_in[13];
    const float* Wg     = (const float*)d_in[14];
    const float* bg     = (const float*)d_in[15];
    const float* Wm     = (const float*)d_in[16];
    const float* Wmu    = (const float*)d_in[17];
    const float* bmu    = (const float*)d_in[18];
    const float* Wstd   = (const float*)d_in[19];
    const float* bstd   = (const float*)d_in[20];

    float *Hin, *Hv, *gh, *bout;
    __half *msg, *giAll, *HinR, *HvR, *Xpad, *Wx32, *Whh3R, *WmsgR, *WoutR;
    cudaGetSymbolAddress((void**)&Hin,   g_Hin);
    cudaGetSymbolAddress((void**)&Hv,    g_Hv);
    cudaGetSymbolAddress((void**)&gh,    g_gh);
    cudaGetSymbolAddress((void**)&bout,  g_bout);
    cudaGetSymbolAddress((void**)&msg,   g_msg);
    cudaGetSymbolAddress((void**)&giAll, g_giAll);
    cudaGetSymbolAddress((void**)&HinR,  g_HinR);
    cudaGetSymbolAddress((void**)&HvR,   g_HvR);
    cudaGetSymbolAddress((void**)&Xpad,  g_Xpad);
    cudaGetSymbolAddress((void**)&Wx32,  g_Wx32);
    cudaGetSymbolAddress((void**)&Whh3R, g_Whh3R);
    cudaGetSymbolAddress((void**)&WmsgR, g_WmsgR);
    cudaGetSymbolAddress((void**)&WoutR, g_WoutR);

    __half* WhhcR = Whh3R;
    __half* WhhlR = Whh3R + (long)G3 * HDIM;
    __half* WhhrR = Whh3R + 2L * G3 * HDIM;

    cudaMemsetAsync(Hin, 0, sizeof(float) * 7LL * BATCH * HDIM, 0);

    pack_xpad<<<(13 * BATCH * 32) / 256, 256>>>(X, adj, Xpad);
    pack_wx32<<<(G3 * 32) / 256, 256>>>(W_ih_c, Wx32,               27);
    pack_wx32<<<(G3 * 32) / 256, 256>>>(W_ih_l, Wx32 + (long)G3*32, 27);
    pack_wx32<<<(G3 * 32) / 256, 256>>>(W_ih_r, Wx32 + 2L*G3*32,    23);
    pack_msgw<<<(NMSG * HDIM) / 256, 256>>>(Wg, Wm, WmsgR);

    half_copy3<<<(3 * G3 * HDIM) / 256, 256>>>(W_hh_c, W_hh_l, W_hh_r,
                                               Whh3R, G3 * HDIM);
    half_copy2<<<(2 * 256 * HDIM) / 256, 256>>>(Wmu, Wstd, WoutR, 256 * HDIM);
    cudaMemcpyAsync(bout,       bmu,  256 * sizeof(float), cudaMemcpyDeviceToDevice, 0);
    cudaMemcpyAsync(bout + 256, bstd, 256 * sizeof(float), cudaMemcpyDeviceToDevice, 0);

    // gi projections (K=32 halves -> single K-tile), fp16 output (act=3)
    const long SEG = 6LL * BATCH;
    dim3 gGI6(G3 / BN, (6 * BATCH) / BM);
    dim3 gGI1(G3 / BN, BATCH / BM);
    hgemm_nt<<<gGI6, 256>>>(Xpad,                Wx32,               b_ih_c,
                            (float*)giAll,               G3, 32, 3);
    hgemm_nt<<<gGI6, 256>>>(Xpad + SEG * 32,     Wx32 + (long)G3*32, b_ih_l,
                            (float*)(giAll + SEG * G3),  G3, 32, 3);
    hgemm_nt<<<gGI1, 256>>>(Xpad + 2 * SEG * 32, Wx32 + 2L*G3*32,    b_ih_r,
                            (float*)(giAll + 2 * SEG * G3), G3, 32, 3);

    dim3 gGH(G3 / BN, BATCH / BM);             // (24, 16)
    dim3 gMS(NMSG / BN, BATCH / BM);           // (32, 16)
    dim3 gOUT(512 / BN, BATCH / BM);           // (4, 16)
    const int EW = (BATCH * HDIM) / 256;       // 8192

    for (int v = 6; v >= 0; v--) {
        const __half* WhhR = (v == 0) ? WhhrR : WhhcR;
        const float* bhh   = (v == 0) ? b_hh_r : b_hh_c;
        const __half* gi1  = (v == 0) ? (giAll + 2 * SEG * G3)
                                      : (giAll + (long)(v - 1) * BATCH * G3);

        // GRU 1
        if (v == 6) {
            gru_combine_bias<<<EW, 256>>>(gi1, bhh, Hv, HvR);
        } else {
            float* Hin_v = Hin + (long)v * BATCH * HDIM;
            hgemm_nt<<<gGH, 256>>>(HinR, WhhR, bhh, gh, G3, HDIM, 0);
            if (v == 0) {
                gru_combine_r<0><<<EW, 256>>>(gi1, gh, Hin_v, Hv, HvR);
            } else {
                gru_combine_r<1><<<EW, 256>>>(gi1, gh, Hin_v, Hv, HvR);
            }
        }

        if (v > 0) {
            // GRU 2 (self-loop)
            const __half* gi2 = giAll + (SEG + (long)(v - 1) * BATCH) * G3;
            hgemm_nt<<<gGH, 256>>>(HvR, WhhlR, b_hh_l, gh, G3, HDIM, 0);
            gru_combine_r<0><<<EW, 256>>>(gi2, gh, Hv, Hv, HvR);

            // sender projections (fp16 out), then push to receivers
            hgemm_nt<<<gMS, 256>>>(HvR, WmsgR, nullptr, (float*)msg, NMSG, HDIM, 3);
            msg_scatter_all<<<EW, 256>>>(msg, adj, bg, Hin, HinR, v);
        }
    }

    // fused mu/std output GEMM (act=2 split epilogue)
    hgemm_nt<<<gOUT, 256>>>(HvR, WoutR, bout, (float*)d_out, 512, HDIM, 2);
}

// round 14
// speedup vs baseline: 1.1702x; 1.0107x over previous
#include <cuda_runtime.h>
#include <cuda_fp16.h>
#include <math.h>
#include <stdint.h>

#define BATCH 2048
#define HDIM  1024
#define G3    3072
#define NMSG  4096

// ---------------- scratch (static device globals; no allocation) ----------------
__device__ float g_Hin[7LL * BATCH * HDIM];
__device__ __align__(16) __half g_gh[(long)BATCH * G3];       // fp16 staging
__device__ __align__(16) __half g_msg[(long)BATCH * NMSG];    // fp16 staging
__device__ __align__(16) __half g_giAll[13LL * BATCH * G3];   // fp16 staging
__device__ __align__(16) __half g_HinR[(long)BATCH * HDIM];   // fp16 A for GRU1
__device__ __align__(16) __half g_HvR[(long)BATCH * HDIM];    // fp16 hidden (carry + GEMM A)
__device__ __align__(16) __half g_Xpad[13LL * BATCH * 32];
__device__ __align__(16) __half g_Wx32[3LL * G3 * 32];
__device__ __align__(16) __half g_Whh3R[3LL * G3 * HDIM];     // [c|l|r]
__device__ __align__(16) __half g_WmsgR[(long)NMSG * HDIM];
__device__ __align__(16) __half g_WoutR[512L * HDIM];         // [Wmu;Wstd]
__device__ float g_bout[512];                                  // [bmu;bstd]

__device__ __forceinline__ float sigmoidf(float x) { return 1.f / (1.f + expf(-x)); }
__device__ __forceinline__ float softplusf(float x) {
    return (x > 20.f) ? x : log1pf(expf(x));
}

// ---------------- packing (emit fp16 operands) ----------------
__global__ void pack_xpad(const float* __restrict__ X, const int* __restrict__ adj,
                          __half* __restrict__ Xp) {
    int idx = blockIdx.x * blockDim.x + threadIdx.x;
    if (idx >= 13 * BATCH * 32) return;
    int slot = idx / (BATCH * 32);
    int rem  = idx - slot * (BATCH * 32);
    int b = rem >> 5, k = rem & 31;
    float v = 0.f;
    if (slot < 6) {
        int node = slot + 1;
        if (k < 27) v = X[(long)b * 189 + node * 27 + k];
    } else if (slot < 12) {
        int node = slot - 5;
        if (k < 27 && adj[(long)b * 49 + node * 8] > 0)
            v = X[(long)b * 189 + node * 27 + k];
    } else {
        if (k < 23) v = X[(long)b * 189 + k];
    }
    Xp[idx] = __float2half_rn(v);
}

__global__ void pack_wx32(const float* __restrict__ W, __half* __restrict__ P, int K) {
    int idx = blockIdx.x * blockDim.x + threadIdx.x;
    if (idx >= G3 * 32) return;
    int j = idx >> 5, k = idx & 31;
    P[idx] = __float2half_rn((k < K) ? W[j * K + k] : 0.f);
}

__global__ void pack_msgw(const float* __restrict__ Wg, const float* __restrict__ Wm,
                          __half* __restrict__ P) {
    int idx = blockIdx.x * blockDim.x + threadIdx.x;
    int j = idx >> 10, k = idx & 1023;
    float v;
    if (j < 1024)       v = Wg[j * 2048 + k];
    else if (j < 2048)  v = Wg[(j - 1024) * 2048 + 1024 + k];
    else if (j < 3072)  v = Wm[(j - 2048) * 2048 + k];
    else                v = Wm[(j - 3072) * 2048 + 1024 + k];
    P[idx] = __float2half_rn(v);
}

__global__ void half_copy3(const float* __restrict__ a, const float* __restrict__ b,
                           const float* __restrict__ c, __half* __restrict__ out,
                           int n) {
    int idx = blockIdx.x * blockDim.x + threadIdx.x;
    if (idx >= 3 * n) return;
    int seg = idx / n, r = idx - seg * n;
    const float* src = (seg == 0) ? a : (seg == 1) ? b : c;
    out[idx] = __float2half_rn(src[r]);
}

__global__ void half_copy2(const float* __restrict__ a, const float* __restrict__ b,
                           __half* __restrict__ out, int n) {
    int idx = blockIdx.x * blockDim.x + threadIdx.x;
    if (idx >= 2 * n) return;
    out[idx] = __float2half_rn(idx < n ? a[idx] : b[idx - n]);
}

// ---------------- GRU elementwise combine; gi/gh fp16; carry via fp16 hoR ---------
// HP_MODE: 0 = hp from f32 buffer (Hin_v), 1 = hp from fp16 hoR (in-place carry)
template<int HP_MODE>
__global__ __launch_bounds__(256) void gru_combine_r(
    const __half* __restrict__ gi, const __half* __restrict__ gh,
    const float* __restrict__ hpf, __half* __restrict__ hoR)
{
    int idx = blockIdx.x * 256 + threadIdx.x;
    int b = idx >> 10, h = idx & 1023;
    long base = (long)b * G3 + h;
    float ir = __half2float(gi[base]);
    float iz = __half2float(gi[base + 1024]);
    float in_ = __half2float(gi[base + 2048]);
    float hr = __half2float(gh[base]);
    float hz = __half2float(gh[base + 1024]);
    float hn = __half2float(gh[base + 2048]);
    float hp = (HP_MODE == 0) ? hpf[idx] : __half2float(hoR[idx]);
    float r = sigmoidf(ir + hr);
    float z = sigmoidf(iz + hz);
    float n = tanhf(in_ + r * hn);
    float o = (1.f - z) * n + z * hp;
    hoR[idx] = __float2half_rn(o);
}

// v=6 GRU1: gh = bias (H_in = 0), hp = 0
__global__ __launch_bounds__(256) void gru_combine_bias(
    const __half* __restrict__ gi, const float* __restrict__ bhh,
    __half* __restrict__ hoR)
{
    int idx = blockIdx.x * 256 + threadIdx.x;
    int b = idx >> 10, h = idx & 1023;
    long base = (long)b * G3 + h;
    float ir = __half2float(gi[base]);
    float iz = __half2float(gi[base + 1024]);
    float in_ = __half2float(gi[base + 2048]);
    float hr = bhh[h], hz = bhh[1024 + h], hn = bhh[2048 + h];
    float r = sigmoidf(ir + hr);
    float z = sigmoidf(iz + hz);
    float n = tanhf(in_ + r * hn);
    hoR[idx] = __float2half_rn((1.f - z) * n);
}

// ---------------- message push: 3 combos precomputed; Mg is fp16 ----------
__global__ __launch_bounds__(256) void msg_scatter_all(
    const __half* __restrict__ Mg, const int* __restrict__ adj,
    const float* __restrict__ bg, float* __restrict__ HinBase,
    __half* __restrict__ HinR, int S)
{
    int idx = blockIdx.x * 256 + threadIdx.x;
    int b = idx >> 10, h = idx & 1023;
    const __half* M = Mg + (long)b * NMSG;
    float Av = __half2float(M[h]);
    float Bv = __half2float(M[1024 + h]);
    float Cv = __half2float(M[2048 + h]);
    float Dv = __half2float(M[3072 + h]);
    float bgh = bg[h];
    float c10 = sigmoidf(Av + bgh) * Cv;
    float c01 = sigmoidf(Bv + bgh) * Dv;
    float c11 = sigmoidf(Av + Bv + bgh) * (Cv + Dv);
    const int* arow = adj + (long)b * 49;
    for (int u = 0; u < S; u++) {
        bool fp = arow[S * 7 + u] > 0;
        bool fs = arow[u * 7 + S] > 0;
        float add = fp ? (fs ? c11 : c10) : (fs ? c01 : 0.f);
        long o = (long)u * BATCH * HDIM + idx;
        float val = HinBase[o] + add;
        HinBase[o] = val;
        if (u == S - 1) HinR[idx] = __float2half_rn(val);
    }
}

// ---------------- fp16 mma.sync GEMM: C[M,N] = A[M,K] * B[N,K]^T ----------------
// act: 0 = f32 out, 2 = split mu/std epilogue (f32), 3 = fp16 out.
#define BM 128
#define BN 128
#define KS 20   // row stride in u32 (16 data + 4 pad)

__global__ __launch_bounds__(256, 2) void hgemm_nt(
    const __half* __restrict__ A, const __half* __restrict__ B,
    const float* __restrict__ bias, float* __restrict__ C,
    int N, int K, int act)
{
    __shared__ unsigned As[2][BM][KS];
    __shared__ unsigned Bs[2][BN][KS];

    const int tid  = threadIdx.x;
    const int lane = tid & 31;
    const int warp = tid >> 5;
    const int wm   = warp >> 1;
    const int wn   = warp & 1;
    const long bm  = (long)blockIdx.y * BM;
    const long bn  = (long)blockIdx.x * BN;

    const int lrow = tid >> 2;
    const int lcolh = (tid & 3) << 3;
    const int lcolu = (tid & 3) << 2;
    const __half* Aptr = A + (bm + lrow) * K + lcolh;
    const __half* Bptr = B + (bn + lrow) * K + lcolh;

    float acc[2][8][4];
#pragma unroll
    for (int i = 0; i < 2; i++)
#pragma unroll
        for (int j = 0; j < 8; j++)
#pragma unroll
            for (int q = 0; q < 4; q++) acc[i][j][q] = 0.f;

    {
#pragma unroll
        for (int r = 0; r < 2; r++) {
            *(uint4*)&As[0][lrow + r * 64][lcolu] =
                *(const uint4*)(Aptr + (long)(r * 64) * K);
            *(uint4*)&Bs[0][lrow + r * 64][lcolu] =
                *(const uint4*)(Bptr + (long)(r * 64) * K);
        }
    }
    __syncthreads();

    const int nt = K / 32;
    const int gr = lane >> 2;
    const int gk = lane & 3;
    uint4 pa[2], pb[2];

    for (int t = 0; t < nt; t++) {
        const int cur = t & 1, nxt = cur ^ 1;
        const bool more = (t + 1 < nt);
        if (more) {
            int koff = (t + 1) * 32;
#pragma unroll
            for (int r = 0; r < 2; r++) {
                pa[r] = *(const uint4*)(Aptr + (long)(r * 64) * K + koff);
                pb[r] = *(const uint4*)(Bptr + (long)(r * 64) * K + koff);
            }
        }
#pragma unroll
        for (int k16 = 0; k16 < 2; k16++) {
            const int kb = k16 * 8;
            unsigned a[2][4], b[8][2];
#pragma unroll
            for (int mt = 0; mt < 2; mt++) {
                int m = wm * 32 + mt * 16 + gr;
                a[mt][0] = As[cur][m][kb + gk];
                a[mt][1] = As[cur][m + 8][kb + gk];
                a[mt][2] = As[cur][m][kb + gk + 4];
                a[mt][3] = As[cur][m + 8][kb + gk + 4];
            }
#pragma unroll
            for (int ntile = 0; ntile < 8; ntile++) {
                int n = wn * 64 + ntile * 8 + gr;
                b[ntile][0] = Bs[cur][n][kb + gk];
                b[ntile][1] = Bs[cur][n][kb + gk + 4];
            }
#pragma unroll
            for (int mt = 0; mt < 2; mt++)
#pragma unroll
                for (int ntile = 0; ntile < 8; ntile++) {
                    asm volatile(
                        "mma.sync.aligned.m16n8k16.row.col.f32.f16.f16.f32 "
                        "{%0,%1,%2,%3}, {%4,%5,%6,%7}, {%8,%9}, {%0,%1,%2,%3};\n"
                        : "+f"(acc[mt][ntile][0]), "+f"(acc[mt][ntile][1]),
                          "+f"(acc[mt][ntile][2]), "+f"(acc[mt][ntile][3])
                        : "r"(a[mt][0]), "r"(a[mt][1]), "r"(a[mt][2]), "r"(a[mt][3]),
                          "r"(b[ntile][0]), "r"(b[ntile][1]));
                }
        }
        if (more) {
#pragma unroll
            for (int r = 0; r < 2; r++) {
                *(uint4*)&As[nxt][lrow + r * 64][lcolu] = pa[r];
                *(uint4*)&Bs[nxt][lrow + r * 64][lcolu] = pb[r];
            }
        }
        __syncthreads();
    }

    const int gc2 = (lane & 3) * 2;
#pragma unroll
    for (int mt = 0; mt < 2; mt++) {
        long row0 = bm + wm * 32 + mt * 16 + gr;
#pragma unroll
        for (int ntile = 0; ntile < 8; ntile++) {
            int col = bn + wn * 64 + ntile * 8 + gc2;
            float b0 = bias ? bias[col] : 0.f;
            float b1 = bias ? bias[col + 1] : 0.f;
            float2 v0, v1;
            v0.x = acc[mt][ntile][0] + b0; v0.y = acc[mt][ntile][1] + b1;
            v1.x = acc[mt][ntile][2] + b0; v1.y = acc[mt][ntile][3] + b1;
            if (act == 3) {
                __half* Ch = (__half*)C;
                __half2 h0 = __floats2half2_rn(v0.x, v0.y);
                __half2 h1 = __floats2half2_rn(v1.x, v1.y);
                *(__half2*)(Ch + row0 * N + col)       = h0;
                *(__half2*)(Ch + (row0 + 8) * N + col) = h1;
            } else if (act == 2) {
                float* dst;
                if (col < 256) {
                    dst = C + row0 * 256 + col;
                } else {
                    dst = C + 2048L * 256 + row0 * 256 + (col - 256);
                    v0.x = softplusf(v0.x); v0.y = softplusf(v0.y);
                    v1.x = softplusf(v1.x); v1.y = softplusf(v1.y);
                }
                *(float2*)dst             = v0;
                *(float2*)(dst + 8 * 256) = v1;
            } else {
                *(float2*)(C + row0 * N + col)       = v0;
                *(float2*)(C + (row0 + 8) * N + col) = v1;
            }
        }
    }
}

// ---------------- orchestration ----------------
extern "C" void kernel_launch(void* const* d_in, const int* in_sizes, int n_in,
                              void* d_out, int out_size)
{
    const float* X      = (const float*)d_in[0];
    const int*   adj    = (const int*)  d_in[1];
    const float* W_ih_c = (const float*)d_in[2];
    const float* W_hh_c = (const float*)d_in[3];
    const float* b_ih_c = (const float*)d_in[4];
    const float* b_hh_c = (const float*)d_in[5];
    const float* W_ih_l = (const float*)d_in[6];
    const float* W_hh_l = (const float*)d_in[7];
    const float* b_ih_l = (const float*)d_in[8];
    const float* b_hh_l = (const float*)d_in[9];
    const float* W_ih_r = (const float*)d_in[10];
    const float* W_hh_r = (const float*)d_in[11];
    const float* b_ih_r = (const float*)d_in[12];
    const float* b_hh_r = (const float*)d_in[13];
    const float* Wg     = (const float*)d_in[14];
    const float* bg     = (const float*)d_in[15];
    const float* Wm     = (const float*)d_in[16];
    const float* Wmu    = (const float*)d_in[17];
    const float* bmu    = (const float*)d_in[18];
    const float* Wstd   = (const float*)d_in[19];
    const float* bstd   = (const float*)d_in[20];

    float *Hin, *bout;
    __half *gh, *msg, *giAll, *HinR, *HvR, *Xpad, *Wx32, *Whh3R, *WmsgR, *WoutR;
    cudaGetSymbolAddress((void**)&Hin,   g_Hin);
    cudaGetSymbolAddress((void**)&bout,  g_bout);
    cudaGetSymbolAddress((void**)&gh,    g_gh);
    cudaGetSymbolAddress((void**)&msg,   g_msg);
    cudaGetSymbolAddress((void**)&giAll, g_giAll);
    cudaGetSymbolAddress((void**)&HinR,  g_HinR);
    cudaGetSymbolAddress((void**)&HvR,   g_HvR);
    cudaGetSymbolAddress((void**)&Xpad,  g_Xpad);
    cudaGetSymbolAddress((void**)&Wx32,  g_Wx32);
    cudaGetSymbolAddress((void**)&Whh3R, g_Whh3R);
    cudaGetSymbolAddress((void**)&WmsgR, g_WmsgR);
    cudaGetSymbolAddress((void**)&WoutR, g_WoutR);

    __half* WhhcR = Whh3R;
    __half* WhhlR = Whh3R + (long)G3 * HDIM;
    __half* WhhrR = Whh3R + 2L * G3 * HDIM;

    cudaMemsetAsync(Hin, 0, sizeof(float) * 7LL * BATCH * HDIM, 0);

    pack_xpad<<<(13 * BATCH * 32) / 256, 256>>>(X, adj, Xpad);
    pack_wx32<<<(G3 * 32) / 256, 256>>>(W_ih_c, Wx32,               27);
    pack_wx32<<<(G3 * 32) / 256, 256>>>(W_ih_l, Wx32 + (long)G3*32, 27);
    pack_wx32<<<(G3 * 32) / 256, 256>>>(W_ih_r, Wx32 + 2L*G3*32,    23);
    pack_msgw<<<(NMSG * HDIM) / 256, 256>>>(Wg, Wm, WmsgR);

    half_copy3<<<(3 * G3 * HDIM) / 256, 256>>>(W_hh_c, W_hh_l, W_hh_r,
                                               Whh3R, G3 * HDIM);
    half_copy2<<<(2 * 256 * HDIM) / 256, 256>>>(Wmu, Wstd, WoutR, 256 * HDIM);
    cudaMemcpyAsync(bout,       bmu,  256 * sizeof(float), cudaMemcpyDeviceToDevice, 0);
    cudaMemcpyAsync(bout + 256, bstd, 256 * sizeof(float), cudaMemcpyDeviceToDevice, 0);

    // gi projections (K=32 halves -> single K-tile), fp16 output (act=3)
    const long SEG = 6LL * BATCH;
    dim3 gGI6(G3 / BN, (6 * BATCH) / BM);
    dim3 gGI1(G3 / BN, BATCH / BM);
    hgemm_nt<<<gGI6, 256>>>(Xpad,                Wx32,               b_ih_c,
                            (float*)giAll,                  G3, 32, 3);
    hgemm_nt<<<gGI6, 256>>>(Xpad + SEG * 32,     Wx32 + (long)G3*32, b_ih_l,
                            (float*)(giAll + SEG * G3),     G3, 32, 3);
    hgemm_nt<<<gGI1, 256>>>(Xpad + 2 * SEG * 32, Wx32 + 2L*G3*32,    b_ih_r,
                            (float*)(giAll + 2 * SEG * G3), G3, 32, 3);

    dim3 gGH(G3 / BN, BATCH / BM);             // (24, 16)
    dim3 gMS(NMSG / BN, BATCH / BM);           // (32, 16)
    dim3 gOUT(512 / BN, BATCH / BM);           // (4, 16)
    const int EW = (BATCH * HDIM) / 256;       // 8192

    for (int v = 6; v >= 0; v--) {
        const __half* WhhR = (v == 0) ? WhhrR : WhhcR;
        const float* bhh   = (v == 0) ? b_hh_r : b_hh_c;
        const __half* gi1  = (v == 0) ? (giAll + 2 * SEG * G3)
                                      : (giAll + (long)(v - 1) * BATCH * G3);

        // GRU 1
        if (v == 6) {
            gru_combine_bias<<<EW, 256>>>(gi1, bhh, HvR);
        } else {
            float* Hin_v = Hin + (long)v * BATCH * HDIM;
            hgemm_nt<<<gGH, 256>>>(HinR, WhhR, bhh, (float*)gh, G3, HDIM, 3);
            // hp from f32 Hin_v; writes HvR
            gru_combine_r<0><<<EW, 256>>>(gi1, gh, Hin_v, HvR);
        }

        if (v > 0) {
            // GRU 2 (self-loop): hp = HvR (fp16 carry, in-place)
            const __half* gi2 = giAll + (SEG + (long)(v - 1) * BATCH) * G3;
            hgemm_nt<<<gGH, 256>>>(HvR, WhhlR, b_hh_l, (float*)gh, G3, HDIM, 3);
            gru_combine_r<1><<<EW, 256>>>(gi2, gh, nullptr, HvR);

            // sender projections (fp16 out), then push to receivers
            hgemm_nt<<<gMS, 256>>>(HvR, WmsgR, nullptr, (float*)msg, NMSG, HDIM, 3);
            msg_scatter_all<<<EW, 256>>>(msg, adj, bg, Hin, HinR, v);
        }
    }

    // fused mu/std output GEMM (act=2 split epilogue)
    hgemm_nt<<<gOUT, 256>>>(HvR, WoutR, bout, (float*)d_out, 512, HDIM, 2);
}

// round 15
// speedup vs baseline: 1.1797x; 1.0081x over previous
#include <cuda_runtime.h>
#include <cuda_fp16.h>
#include <math.h>
#include <stdint.h>

#define BATCH 2048
#define HDIM  1024
#define G3    3072
#define NMSG  4096

// ---------------- scratch (static device globals; no allocation) ----------------
__device__ __align__(16) __half g_gh[(long)BATCH * G3];        // fp16 staging
__device__ __align__(16) __half g_msgAll[6LL * BATCH * NMSG];  // all sender projections
__device__ __align__(16) __half g_giAll[13LL * BATCH * G3];    // fp16 staging
__device__ __align__(16) __half g_HinR[(long)BATCH * HDIM];    // fp16 H_in (GEMM A + hp)
__device__ __align__(16) __half g_HvR[(long)BATCH * HDIM];     // fp16 hidden (carry + GEMM A)
__device__ __align__(16) __half g_Xpad[13LL * BATCH * 32];
__device__ __align__(16) __half g_Wx32[3LL * G3 * 32];
__device__ __align__(16) __half g_Whh3R[3LL * G3 * HDIM];      // [c|l|r]
__device__ __align__(16) __half g_WmsgR[(long)NMSG * HDIM];
__device__ __align__(16) __half g_WoutR[512L * HDIM];          // [Wmu;Wstd]
__device__ float g_bout[512];                                   // [bmu;bstd]

__device__ __forceinline__ float sigmoidf(float x) { return 1.f / (1.f + expf(-x)); }
__device__ __forceinline__ float softplusf(float x) {
    return (x > 20.f) ? x : log1pf(expf(x));
}

// ---------------- packing (emit fp16 operands) ----------------
__global__ void pack_xpad(const float* __restrict__ X, const int* __restrict__ adj,
                          __half* __restrict__ Xp) {
    int idx = blockIdx.x * blockDim.x + threadIdx.x;
    if (idx >= 13 * BATCH * 32) return;
    int slot = idx / (BATCH * 32);
    int rem  = idx - slot * (BATCH * 32);
    int b = rem >> 5, k = rem & 31;
    float v = 0.f;
    if (slot < 6) {
        int node = slot + 1;
        if (k < 27) v = X[(long)b * 189 + node * 27 + k];
    } else if (slot < 12) {
        int node = slot - 5;
        if (k < 27 && adj[(long)b * 49 + node * 8] > 0)
            v = X[(long)b * 189 + node * 27 + k];
    } else {
        if (k < 23) v = X[(long)b * 189 + k];
    }
    Xp[idx] = __float2half_rn(v);
}

__global__ void pack_wx32(const float* __restrict__ W, __half* __restrict__ P, int K) {
    int idx = blockIdx.x * blockDim.x + threadIdx.x;
    if (idx >= G3 * 32) return;
    int j = idx >> 5, k = idx & 31;
    P[idx] = __float2half_rn((k < K) ? W[j * K + k] : 0.f);
}

__global__ void pack_msgw(const float* __restrict__ Wg, const float* __restrict__ Wm,
                          __half* __restrict__ P) {
    int idx = blockIdx.x * blockDim.x + threadIdx.x;
    int j = idx >> 10, k = idx & 1023;
    float v;
    if (j < 1024)       v = Wg[j * 2048 + k];
    else if (j < 2048)  v = Wg[(j - 1024) * 2048 + 1024 + k];
    else if (j < 3072)  v = Wm[(j - 2048) * 2048 + k];
    else                v = Wm[(j - 3072) * 2048 + 1024 + k];
    P[idx] = __float2half_rn(v);
}

__global__ void half_copy3(const float* __restrict__ a, const float* __restrict__ b,
                           const float* __restrict__ c, __half* __restrict__ out,
                           int n) {
    int idx = blockIdx.x * blockDim.x + threadIdx.x;
    if (idx >= 3 * n) return;
    int seg = idx / n, r = idx - seg * n;
    const float* src = (seg == 0) ? a : (seg == 1) ? b : c;
    out[idx] = __float2half_rn(src[r]);
}

__global__ void half_copy2(const float* __restrict__ a, const float* __restrict__ b,
                           __half* __restrict__ out, int n) {
    int idx = blockIdx.x * blockDim.x + threadIdx.x;
    if (idx >= 2 * n) return;
    out[idx] = __float2half_rn(idx < n ? a[idx] : b[idx - n]);
}

// ---------------- GRU elementwise combine; gi/gh fp16; hp fp16 ----------------
// hp == nullptr  =>  hp = 0 path not used here (see gru_combine_bias)
__global__ __launch_bounds__(256) void gru_combine_r(
    const __half* __restrict__ gi, const __half* __restrict__ gh,
    const __half* __restrict__ hp, __half* __restrict__ hoR)
{
    int idx = blockIdx.x * 256 + threadIdx.x;
    int b = idx >> 10, h = idx & 1023;
    long base = (long)b * G3 + h;
    float ir = __half2float(gi[base]);
    float iz = __half2float(gi[base + 1024]);
    float in_ = __half2float(gi[base + 2048]);
    float hr = __half2float(gh[base]);
    float hz = __half2float(gh[base + 1024]);
    float hn = __half2float(gh[base + 2048]);
    float hpv = __half2float(hp[idx]);
    float r = sigmoidf(ir + hr);
    float z = sigmoidf(iz + hz);
    float n = tanhf(in_ + r * hn);
    float o = (1.f - z) * n + z * hpv;
    hoR[idx] = __float2half_rn(o);
}

// v=6 GRU1: gh = bias (H_in = 0), hp = 0
__global__ __launch_bounds__(256) void gru_combine_bias(
    const __half* __restrict__ gi, const float* __restrict__ bhh,
    __half* __restrict__ hoR)
{
    int idx = blockIdx.x * 256 + threadIdx.x;
    int b = idx >> 10, h = idx & 1023;
    long base = (long)b * G3 + h;
    float ir = __half2float(gi[base]);
    float iz = __half2float(gi[base + 1024]);
    float in_ = __half2float(gi[base + 2048]);
    float hr = bhh[h], hz = bhh[1024 + h], hn = bhh[2048 + h];
    float r = sigmoidf(ir + hr);
    float z = sigmoidf(iz + hz);
    float n = tanhf(in_ + r * hn);
    hoR[idx] = __float2half_rn((1.f - z) * n);
}

// ---------------- lazy gather: H_in[v] = sum over senders S > v ----------------
__global__ __launch_bounds__(256) void msg_gather(
    const __half* __restrict__ msgAll, const int* __restrict__ adj,
    const float* __restrict__ bg, __half* __restrict__ HinR, int v)
{
    int idx = blockIdx.x * 256 + threadIdx.x;    // BATCH*HDIM
    int b = idx >> 10, h = idx & 1023;
    const int* arow = adj + (long)b * 49;
    float bgh = bg[h];
    float acc = 0.f;
    for (int S = v + 1; S <= 6; S++) {
        bool fp = arow[S * 7 + v] > 0;
        bool fs = arow[v * 7 + S] > 0;
        if (fp | fs) {
            const __half* M = msgAll + ((long)(S - 1) * BATCH + b) * NMSG;
            float a = 0.f, m = 0.f;
            if (fp) { a += __half2float(M[h]);        m += __half2float(M[2048 + h]); }
            if (fs) { a += __half2float(M[1024 + h]); m += __half2float(M[3072 + h]); }
            acc += sigmoidf(a + bgh) * m;
        }
    }
    HinR[idx] = __float2half_rn(acc);
}

// ---------------- fp16 mma.sync GEMM: C[M,N] = A[M,K] * B[N,K]^T ----------------
// act: 2 = split mu/std epilogue (f32), 3 = fp16 out.
#define BM 128
#define BN 128
#define KS 20   // row stride in u32 (16 data + 4 pad)

__global__ __launch_bounds__(256, 2) void hgemm_nt(
    const __half* __restrict__ A, const __half* __restrict__ B,
    const float* __restrict__ bias, float* __restrict__ C,
    int N, int K, int act)
{
    __shared__ unsigned As[2][BM][KS];
    __shared__ unsigned Bs[2][BN][KS];

    const int tid  = threadIdx.x;
    const int lane = tid & 31;
    const int warp = tid >> 5;
    const int wm   = warp >> 1;
    const int wn   = warp & 1;
    const long bm  = (long)blockIdx.y * BM;
    const long bn  = (long)blockIdx.x * BN;

    const int lrow = tid >> 2;
    const int lcolh = (tid & 3) << 3;
    const int lcolu = (tid & 3) << 2;
    const __half* Aptr = A + (bm + lrow) * K + lcolh;
    const __half* Bptr = B + (bn + lrow) * K + lcolh;

    float acc[2][8][4];
#pragma unroll
    for (int i = 0; i < 2; i++)
#pragma unroll
        for (int j = 0; j < 8; j++)
#pragma unroll
            for (int q = 0; q < 4; q++) acc[i][j][q] = 0.f;

    {
#pragma unroll
        for (int r = 0; r < 2; r++) {
            *(uint4*)&As[0][lrow + r * 64][lcolu] =
                *(const uint4*)(Aptr + (long)(r * 64) * K);
            *(uint4*)&Bs[0][lrow + r * 64][lcolu] =
                *(const uint4*)(Bptr + (long)(r * 64) * K);
        }
    }
    __syncthreads();

    const int nt = K / 32;
    const int gr = lane >> 2;
    const int gk = lane & 3;
    uint4 pa[2], pb[2];

    for (int t = 0; t < nt; t++) {
        const int cur = t & 1, nxt = cur ^ 1;
        const bool more = (t + 1 < nt);
        if (more) {
            int koff = (t + 1) * 32;
#pragma unroll
            for (int r = 0; r < 2; r++) {
                pa[r] = *(const uint4*)(Aptr + (long)(r * 64) * K + koff);
                pb[r] = *(const uint4*)(Bptr + (long)(r * 64) * K + koff);
            }
        }
#pragma unroll
        for (int k16 = 0; k16 < 2; k16++) {
            const int kb = k16 * 8;
            unsigned a[2][4], b[8][2];
#pragma unroll
            for (int mt = 0; mt < 2; mt++) {
                int m = wm * 32 + mt * 16 + gr;
                a[mt][0] = As[cur][m][kb + gk];
                a[mt][1] = As[cur][m + 8][kb + gk];
                a[mt][2] = As[cur][m][kb + gk + 4];
                a[mt][3] = As[cur][m + 8][kb + gk + 4];
            }
#pragma unroll
            for (int ntile = 0; ntile < 8; ntile++) {
                int n = wn * 64 + ntile * 8 + gr;
                b[ntile][0] = Bs[cur][n][kb + gk];
                b[ntile][1] = Bs[cur][n][kb + gk + 4];
            }
#pragma unroll
            for (int mt = 0; mt < 2; mt++)
#pragma unroll
                for (int ntile = 0; ntile < 8; ntile++) {
                    asm volatile(
                        "mma.sync.aligned.m16n8k16.row.col.f32.f16.f16.f32 "
                        "{%0,%1,%2,%3}, {%4,%5,%6,%7}, {%8,%9}, {%0,%1,%2,%3};\n"
                        : "+f"(acc[mt][ntile][0]), "+f"(acc[mt][ntile][1]),
                          "+f"(acc[mt][ntile][2]), "+f"(acc[mt][ntile][3])
                        : "r"(a[mt][0]), "r"(a[mt][1]), "r"(a[mt][2]), "r"(a[mt][3]),
                          "r"(b[ntile][0]), "r"(b[ntile][1]));
                }
        }
        if (more) {
#pragma unroll
            for (int r = 0; r < 2; r++) {
                *(uint4*)&As[nxt][lrow + r * 64][lcolu] = pa[r];
                *(uint4*)&Bs[nxt][lrow + r * 64][lcolu] = pb[r];
            }
        }
        __syncthreads();
    }

    const int gc2 = (lane & 3) * 2;
#pragma unroll
    for (int mt = 0; mt < 2; mt++) {
        long row0 = bm + wm * 32 + mt * 16 + gr;
#pragma unroll
        for (int ntile = 0; ntile < 8; ntile++) {
            int col = bn + wn * 64 + ntile * 8 + gc2;
            float b0 = bias ? bias[col] : 0.f;
            float b1 = bias ? bias[col + 1] : 0.f;
            float2 v0, v1;
            v0.x = acc[mt][ntile][0] + b0; v0.y = acc[mt][ntile][1] + b1;
            v1.x = acc[mt][ntile][2] + b0; v1.y = acc[mt][ntile][3] + b1;
            if (act == 3) {
                __half* Ch = (__half*)C;
                __half2 h0 = __floats2half2_rn(v0.x, v0.y);
                __half2 h1 = __floats2half2_rn(v1.x, v1.y);
                *(__half2*)(Ch + row0 * N + col)       = h0;
                *(__half2*)(Ch + (row0 + 8) * N + col) = h1;
            } else if (act == 2) {
                float* dst;
                if (col < 256) {
                    dst = C + row0 * 256 + col;
                } else {
                    dst = C + 2048L * 256 + row0 * 256 + (col - 256);
                    v0.x = softplusf(v0.x); v0.y = softplusf(v0.y);
                    v1.x = softplusf(v1.x); v1.y = softplusf(v1.y);
                }
                *(float2*)dst             = v0;
                *(float2*)(dst + 8 * 256) = v1;
            } else {
                *(float2*)(C + row0 * N + col)       = v0;
                *(float2*)(C + (row0 + 8) * N + col) = v1;
            }
        }
    }
}

// ---------------- orchestration ----------------
extern "C" void kernel_launch(void* const* d_in, const int* in_sizes, int n_in,
                              void* d_out, int out_size)
{
    const float* X      = (const float*)d_in[0];
    const int*   adj    = (const int*)  d_in[1];
    const float* W_ih_c = (const float*)d_in[2];
    const float* W_hh_c = (const float*)d_in[3];
    const float* b_ih_c = (const float*)d_in[4];
    const float* b_hh_c = (const float*)d_in[5];
    const float* W_ih_l = (const float*)d_in[6];
    const float* W_hh_l = (const float*)d_in[7];
    const float* b_ih_l = (const float*)d_in[8];
    const float* b_hh_l = (const float*)d_in[9];
    const float* W_ih_r = (const float*)d_in[10];
    const float* W_hh_r = (const float*)d_in[11];
    const float* b_ih_r = (const float*)d_in[12];
    const float* b_hh_r = (const float*)d_in[13];
    const float* Wg     = (const float*)d_in[14];
    const float* bg     = (const float*)d_in[15];
    const float* Wm     = (const float*)d_in[16];
    const float* Wmu    = (const float*)d_in[17];
    const float* bmu    = (const float*)d_in[18];
    const float* Wstd   = (const float*)d_in[19];
    const float* bstd   = (const float*)d_in[20];

    float *bout;
    __half *gh, *msgAll, *giAll, *HinR, *HvR, *Xpad, *Wx32, *Whh3R, *WmsgR, *WoutR;
    cudaGetSymbolAddress((void**)&bout,   g_bout);
    cudaGetSymbolAddress((void**)&gh,     g_gh);
    cudaGetSymbolAddress((void**)&msgAll, g_msgAll);
    cudaGetSymbolAddress((void**)&giAll,  g_giAll);
    cudaGetSymbolAddress((void**)&HinR,   g_HinR);
    cudaGetSymbolAddress((void**)&HvR,    g_HvR);
    cudaGetSymbolAddress((void**)&Xpad,   g_Xpad);
    cudaGetSymbolAddress((void**)&Wx32,   g_Wx32);
    cudaGetSymbolAddress((void**)&Whh3R,  g_Whh3R);
    cudaGetSymbolAddress((void**)&WmsgR,  g_WmsgR);
    cudaGetSymbolAddress((void**)&WoutR,  g_WoutR);

    __half* WhhcR = Whh3R;
    __half* WhhlR = Whh3R + (long)G3 * HDIM;
    __half* WhhrR = Whh3R + 2L * G3 * HDIM;

    pack_xpad<<<(13 * BATCH * 32) / 256, 256>>>(X, adj, Xpad);
    pack_wx32<<<(G3 * 32) / 256, 256>>>(W_ih_c, Wx32,               27);
    pack_wx32<<<(G3 * 32) / 256, 256>>>(W_ih_l, Wx32 + (long)G3*32, 27);
    pack_wx32<<<(G3 * 32) / 256, 256>>>(W_ih_r, Wx32 + 2L*G3*32,    23);
    pack_msgw<<<(NMSG * HDIM) / 256, 256>>>(Wg, Wm, WmsgR);

    half_copy3<<<(3 * G3 * HDIM) / 256, 256>>>(W_hh_c, W_hh_l, W_hh_r,
                                               Whh3R, G3 * HDIM);
    half_copy2<<<(2 * 256 * HDIM) / 256, 256>>>(Wmu, Wstd, WoutR, 256 * HDIM);
    cudaMemcpyAsync(bout,       bmu,  256 * sizeof(float), cudaMemcpyDeviceToDevice, 0);
    cudaMemcpyAsync(bout + 256, bstd, 256 * sizeof(float), cudaMemcpyDeviceToDevice, 0);

    // gi projections (K=32 halves -> single K-tile), fp16 output (act=3)
    const long SEG = 6LL * BATCH;
    dim3 gGI6(G3 / BN, (6 * BATCH) / BM);
    dim3 gGI1(G3 / BN, BATCH / BM);
    hgemm_nt<<<gGI6, 256>>>(Xpad,                Wx32,               b_ih_c,
                            (float*)giAll,                  G3, 32, 3);
    hgemm_nt<<<gGI6, 256>>>(Xpad + SEG * 32,     Wx32 + (long)G3*32, b_ih_l,
                            (float*)(giAll + SEG * G3),     G3, 32, 3);
    hgemm_nt<<<gGI1, 256>>>(Xpad + 2 * SEG * 32, Wx32 + 2L*G3*32,    b_ih_r,
                            (float*)(giAll + 2 * SEG * G3), G3, 32, 3);

    dim3 gGH(G3 / BN, BATCH / BM);             // (24, 16)
    dim3 gMS(NMSG / BN, BATCH / BM);           // (32, 16)
    dim3 gOUT(512 / BN, BATCH / BM);           // (4, 16)
    const int EW = (BATCH * HDIM) / 256;       // 8192

    for (int v = 6; v >= 0; v--) {
        const __half* WhhR = (v == 0) ? WhhrR : WhhcR;
        const float* bhh   = (v == 0) ? b_hh_r : b_hh_c;
        const __half* gi1  = (v == 0) ? (giAll + 2 * SEG * G3)
                                      : (giAll + (long)(v - 1) * BATCH * G3);

        // GRU 1
        if (v == 6) {
            gru_combine_bias<<<EW, 256>>>(gi1, bhh, HvR);
        } else {
            // lazy gather of H_in from stored sender projections
            msg_gather<<<EW, 256>>>(msgAll, adj, bg, HinR, v);
            hgemm_nt<<<gGH, 256>>>(HinR, WhhR, bhh, (float*)gh, G3, HDIM, 3);
            gru_combine_r<<<EW, 256>>>(gi1, gh, HinR, HvR);
        }

        if (v > 0) {
            // GRU 2 (self-loop): hp = HvR (fp16 carry, in-place)
            const __half* gi2 = giAll + (SEG + (long)(v - 1) * BATCH) * G3;
            hgemm_nt<<<gGH, 256>>>(HvR, WhhlR, b_hh_l, (float*)gh, G3, HDIM, 3);
            gru_combine_r<<<EW, 256>>>(gi2, gh, HvR, HvR);

            // sender projections stored to msgAll plane S-1 (no scatter)
            hgemm_nt<<<gMS, 256>>>(HvR, WmsgR, nullptr,
                                   (float*)(msgAll + (long)(v - 1) * BATCH * NMSG),
                                   NMSG, HDIM, 3);
        }
    }

    // fused mu/std output GEMM (act=2 split epilogue)
    hgemm_nt<<<gOUT, 256>>>(HvR, WoutR, bout, (float*)d_out, 512, HDIM, 2);
}